// round 2
// baseline (speedup 1.0000x reference)
#include <cuda_runtime.h>
#include <cuda_bf16.h>
#include <cstdint>

#define NMAX 100000
#define GMAX 256
#define HEADS 4

// ---------------- scratch (device globals; no allocation allowed) -------------
__device__ float g_b0[NMAX * 128];
__device__ float g_b1[NMAX * 128];
__device__ float g_b2[NMAX * 128];
__device__ float g_dis[NMAX];
__device__ float g_asrc[NMAX * HEADS];
__device__ float g_adst[NMAX * HEADS];
__device__ float g_m[NMAX * HEADS];
__device__ float g_s[NMAX * HEADS];
__device__ float g_bnsum[128];
__device__ float g_bnsq[128];
__device__ float g_scale[128];
__device__ float g_shift[128];
__device__ float g_pool[GMAX * 64];
__device__ float g_cnt[GMAX];

// ---------------- helpers ----------------
__device__ __forceinline__ float lrelu(float v) { return v > 0.f ? v : 0.2f * v; }

__device__ __forceinline__ void atomicMaxF(float* p, float v) {
    if (v >= 0.f) atomicMax((int*)p, __float_as_int(v));
    else          atomicMin((unsigned int*)p, (unsigned int)__float_as_int(v));
}

// ---------------- kernels ----------------
__global__ void fill_kernel(float* p, float v, int n) {
    int t = blockIdx.x * blockDim.x + threadIdx.x;
    if (t < n) p[t] = v;
}

__global__ void deg_accum_kernel(const int* __restrict__ col, float* deg, int E) {
    int e = blockIdx.x * blockDim.x + threadIdx.x;
    if (e < E) atomicAdd(&deg[col[e]], 1.0f);
}

__global__ void rsqrt_kernel(float* p, int n) {
    int t = blockIdx.x * blockDim.x + threadIdx.x;
    if (t < n) p[t] = rsqrtf(p[t]);
}

// C[M,N] = A[M,K] @ B[K,N].  K multiple of 16, N multiple of 64.
__global__ void gemm_kernel(const float* __restrict__ A, const float* __restrict__ B,
                            float* __restrict__ C, int M, int N, int K) {
    __shared__ float As[16][65];
    __shared__ float Bs[16][64];
    int tid = threadIdx.x;
    int ty = tid >> 4, tx = tid & 15;
    int rowBase = blockIdx.y * 64;
    int colBase = blockIdx.x * 64;
    float acc[4][4] = {};
    for (int k0 = 0; k0 < K; k0 += 16) {
#pragma unroll
        for (int i = 0; i < 4; i++) {
            int idx = tid + i * 256;
            int r = idx >> 4, cc = idx & 15;
            int gr = rowBase + r;
            As[cc][r] = (gr < M) ? A[(size_t)gr * K + k0 + cc] : 0.f;
        }
#pragma unroll
        for (int i = 0; i < 4; i++) {
            int idx = tid + i * 256;
            int r = idx >> 6, cc = idx & 63;
            Bs[r][cc] = B[(size_t)(k0 + r) * N + colBase + cc];
        }
        __syncthreads();
#pragma unroll
        for (int kk = 0; kk < 16; kk++) {
            float a[4], b[4];
#pragma unroll
            for (int m = 0; m < 4; m++) a[m] = As[kk][ty * 4 + m];
#pragma unroll
            for (int n = 0; n < 4; n++) b[n] = Bs[kk][tx * 4 + n];
#pragma unroll
            for (int m = 0; m < 4; m++)
#pragma unroll
                for (int n = 0; n < 4; n++) acc[m][n] += a[m] * b[n];
        }
        __syncthreads();
    }
#pragma unroll
    for (int m = 0; m < 4; m++) {
        int gr = rowBase + ty * 4 + m;
        if (gr >= M) continue;
#pragma unroll
        for (int n = 0; n < 4; n++)
            C[(size_t)gr * N + colBase + tx * 4 + n] = acc[m][n];
    }
}

// GCN aggregation: warp per edge, agg[col] += h[row] * dis[row]*dis[col]
__global__ void gcn_agg_kernel(const float* __restrict__ h, const int* __restrict__ row,
                               const int* __restrict__ col, const float* __restrict__ dis,
                               float* __restrict__ out, int Etot, int Ereal, int d) {
    int gw = (blockIdx.x * blockDim.x + threadIdx.x) >> 5;
    int lane = threadIdx.x & 31;
    if (gw >= Etot) return;
    int r, c;
    if (gw < Ereal) { r = row[gw]; c = col[gw]; }
    else            { r = c = gw - Ereal; }
    float nrm = dis[r] * dis[c];
    const float* hp = h + (size_t)r * d;
    float* op = out + (size_t)c * d;
    for (int j = lane * 4; j < d; j += 128) {
        float4 v = *(const float4*)(hp + j);
        atomicAdd(op + j + 0, v.x * nrm);
        atomicAdd(op + j + 1, v.y * nrm);
        atomicAdd(op + j + 2, v.z * nrm);
        atomicAdd(op + j + 3, v.w * nrm);
    }
}

// BN stats: blockDim.x == d, grid-stride over rows
__global__ void bn_stats_kernel(const float* __restrict__ x, float* sum, float* sq,
                                int Nrows, int d) {
    int c = threadIdx.x;
    float s = 0.f, ss = 0.f;
    for (int r = blockIdx.x; r < Nrows; r += gridDim.x) {
        float v = x[(size_t)r * d + c];
        s += v; ss += v * v;
    }
    atomicAdd(&sum[c], s);
    atomicAdd(&sq[c], ss);
}

__global__ void bn_finalize_kernel(const float* sum, const float* sq,
                                   const float* __restrict__ g, const float* __restrict__ b,
                                   float* scale, float* shift, int d, float invN) {
    int c = threadIdx.x;
    if (c < d) {
        float mu = sum[c] * invN;
        float var = sq[c] * invN - mu * mu;
        float rs = rsqrtf(var + 1e-5f);
        float sc = g[c] * rs;
        scale[c] = sc;
        shift[c] = b[c] - mu * sc;
    }
}

__global__ void bn_apply_kernel(const float* __restrict__ xin, float* __restrict__ y,
                                const float* __restrict__ scale, const float* __restrict__ shift,
                                int total, int d, int relu) {
    int t = blockIdx.x * blockDim.x + threadIdx.x;
    if (t >= total) return;
    int c = t % d;
    float v = xin[t] * scale[c] + shift[c];
    if (relu) v = lrelu(v);
    y[t] = v;
}

// per (node, head): attention coefficients
__global__ void gat_coef_kernel(const float* __restrict__ hg, const float* __restrict__ a_src,
                                const float* __restrict__ a_dst, float* asrc, float* adst,
                                int Nn, int d) {
    int t = blockIdx.x * blockDim.x + threadIdx.x;
    if (t >= Nn * HEADS) return;
    int n = t >> 2, h = t & 3;
    int C = d >> 2;
    const float* hp = hg + (size_t)n * d + h * C;
    const float* as = a_src + h * C;
    const float* ad = a_dst + h * C;
    float s1 = 0.f, s2 = 0.f;
    for (int c = 0; c < C; c++) { float v = hp[c]; s1 += v * as[c]; s2 += v * ad[c]; }
    asrc[t] = s1;
    adst[t] = s2;
}

__global__ void gat_init_ms_kernel(float* m, float* s, int n) {
    int t = blockIdx.x * blockDim.x + threadIdx.x;
    if (t < n) { m[t] = -1e30f; s[t] = 0.f; }
}

__global__ void gat_max_kernel(const float* __restrict__ asrc, const float* __restrict__ adst,
                               const int* __restrict__ row, const int* __restrict__ col,
                               float* m, int Etot, int Ereal) {
    int e = blockIdx.x * blockDim.x + threadIdx.x;
    if (e >= Etot) return;
    int r, c;
    if (e < Ereal) { r = row[e]; c = col[e]; }
    else           { r = c = e - Ereal; }
    float4 as = *(const float4*)(asrc + (size_t)r * 4);
    float4 ad = *(const float4*)(adst + (size_t)c * 4);
    atomicMaxF(&m[c * 4 + 0], lrelu(as.x + ad.x));
    atomicMaxF(&m[c * 4 + 1], lrelu(as.y + ad.y));
    atomicMaxF(&m[c * 4 + 2], lrelu(as.z + ad.z));
    atomicMaxF(&m[c * 4 + 3], lrelu(as.w + ad.w));
}

// warp per edge: accumulate s[col] += ex, num[col] += ex * hg[row]
__global__ void gat_accum_kernel(const float* __restrict__ hg, const float* __restrict__ asrc,
                                 const float* __restrict__ adst, const float* __restrict__ m,
                                 float* s, float* num, const int* __restrict__ row,
                                 const int* __restrict__ col, int Etot, int Ereal, int d) {
    int gw = (blockIdx.x * blockDim.x + threadIdx.x) >> 5;
    int lane = threadIdx.x & 31;
    if (gw >= Etot) return;
    int r, c;
    if (gw < Ereal) { r = row[gw]; c = col[gw]; }
    else            { r = c = gw - Ereal; }
    float ex = 0.f;
    if (lane < 4) {
        float e = asrc[r * 4 + lane] + adst[c * 4 + lane];
        e = lrelu(e);
        ex = __expf(e - m[c * 4 + lane]);
        atomicAdd(&s[c * 4 + lane], ex);
    }
    float ex0 = __shfl_sync(0xffffffffu, ex, 0);
    float ex1 = __shfl_sync(0xffffffffu, ex, 1);
    float ex2 = __shfl_sync(0xffffffffu, ex, 2);
    float ex3 = __shfl_sync(0xffffffffu, ex, 3);
    int C = d >> 2;
    const float* hp = hg + (size_t)r * d;
    float* np = num + (size_t)c * d;
    for (int j = lane * 4; j < d; j += 128) {
        float4 v = *(const float4*)(hp + j);
        int h = j / C;
        float w = (h == 0) ? ex0 : (h == 1) ? ex1 : (h == 2) ? ex2 : ex3;
        atomicAdd(np + j + 0, v.x * w);
        atomicAdd(np + j + 1, v.y * w);
        atomicAdd(np + j + 2, v.z * w);
        atomicAdd(np + j + 3, v.w * w);
    }
}

// x_next = num / s + gat_b + y_residual, then LeakyReLU
__global__ void gat_finalize_kernel(float* __restrict__ numx, const float* __restrict__ s,
                                    const float* __restrict__ gb, const float* __restrict__ y,
                                    int total, int d) {
    int t = blockIdx.x * blockDim.x + threadIdx.x;
    if (t >= total) return;
    int n = t / d, c = t % d;
    int C = d >> 2;
    float v = numx[t] / s[n * 4 + c / C] + gb[c] + y[t];
    numx[t] = lrelu(v);
}

__global__ void pool_accum_kernel(const float* __restrict__ x, const int* __restrict__ batch,
                                  float* sums, int Nn, int d) {
    int t = blockIdx.x * blockDim.x + threadIdx.x;
    if (t >= Nn * d) return;
    int n = t / d, c = t % d;
    atomicAdd(&sums[batch[n] * d + c], x[t]);
}

__global__ void pool_cnt_kernel(const int* __restrict__ batch, float* cnt, int Nn) {
    int n = blockIdx.x * blockDim.x + threadIdx.x;
    if (n < Nn) atomicAdd(&cnt[batch[n]], 1.0f);
}

__global__ void pool_final_kernel(const float* __restrict__ sums, const float* __restrict__ cnt,
                                  float* __restrict__ out, int G, int d) {
    int t = blockIdx.x * blockDim.x + threadIdx.x;
    if (t >= G * d) return;
    int g = t / d;
    out[t] = sums[t] / fmaxf(cnt[g], 1.0f);
}

// ---------------- host orchestration ----------------
static inline int cdiv(int a, int b) { return (a + b - 1) / b; }

static void run_gemm(const float* A, const float* B, float* C, int M, int N, int K) {
    dim3 grid(cdiv(N, 64), cdiv(M, 64));
    gemm_kernel<<<grid, 256>>>(A, B, C, M, N, K);
}

extern "C" void kernel_launch(void* const* d_in, const int* in_sizes, int n_in,
                              void* d_out, int out_size) {
    const float* x_in   = (const float*)d_in[0];
    const int*   ei     = (const int*)d_in[1];
    const int*   batch  = (const int*)d_in[2];
    const float* gcn_w[4], *bn_g[4], *bn_b[4];
    for (int i = 0; i < 4; i++) {
        gcn_w[i] = (const float*)d_in[3 + i * 4 + 0];
        bn_g[i]  = (const float*)d_in[3 + i * 4 + 2];
        bn_b[i]  = (const float*)d_in[3 + i * 4 + 3];
    }
    const float* gat_w[2], *gat_as[2], *gat_ad[2], *gat_b[2];
    for (int j = 0; j < 2; j++) {
        gat_w[j]  = (const float*)d_in[19 + j * 4 + 0];
        gat_as[j] = (const float*)d_in[19 + j * 4 + 1];
        gat_ad[j] = (const float*)d_in[19 + j * 4 + 2];
        gat_b[j]  = (const float*)d_in[19 + j * 4 + 3];
    }
    const int Nn = in_sizes[0] / 16;
    const int E  = in_sizes[1] / 2;
    const int* row = ei;
    const int* col = ei + E;
    const int Etot = E + Nn;
    const int DIMS[5] = {16, 64, 128, 128, 64};

    float *b0, *b1, *b2, *dis, *asrc, *adst, *ms, *ss;
    float *bnsum, *bnsq, *scl, *shf, *pool, *cnt;
    cudaGetSymbolAddress((void**)&b0, g_b0);
    cudaGetSymbolAddress((void**)&b1, g_b1);
    cudaGetSymbolAddress((void**)&b2, g_b2);
    cudaGetSymbolAddress((void**)&dis, g_dis);
    cudaGetSymbolAddress((void**)&asrc, g_asrc);
    cudaGetSymbolAddress((void**)&adst, g_adst);
    cudaGetSymbolAddress((void**)&ms, g_m);
    cudaGetSymbolAddress((void**)&ss, g_s);
    cudaGetSymbolAddress((void**)&bnsum, g_bnsum);
    cudaGetSymbolAddress((void**)&bnsq, g_bnsq);
    cudaGetSymbolAddress((void**)&scl, g_scale);
    cudaGetSymbolAddress((void**)&shf, g_shift);
    cudaGetSymbolAddress((void**)&pool, g_pool);
    cudaGetSymbolAddress((void**)&cnt, g_cnt);

    // degree -> dis = rsqrt(deg), deg initialized to 1 for self-loop
    fill_kernel<<<cdiv(Nn, 256), 256>>>(dis, 1.0f, Nn);
    deg_accum_kernel<<<cdiv(E, 256), 256>>>(col, dis, E);
    rsqrt_kernel<<<cdiv(Nn, 256), 256>>>(dis, Nn);

    const int warpGrid = cdiv(Etot * 32, 256);

    // layer buffer plan:
    //  i=0: xin=x(ext) h=b0 agg=b1 y=b0 hg=b1 num=b2 -> xnext=b2
    //  i=1: xin=b2     h=b0 agg=b1 y=b0              -> xnext=b0
    //  i=2: xin=b0     h=b1 agg=b2 y=b1 hg=b2 num=b0 -> xnext=b0
    //  i=3: xin=b0     h=b1 agg=b2 y=b1              -> final=b1
    const float* xin = x_in;
    float* hbuf[4]   = {b0, b0, b1, b1};
    float* aggbuf[4] = {b1, b1, b2, b2};
    float* hgbuf[4]  = {b1, 0, b2, 0};
    float* numbuf[4] = {b2, 0, b0, 0};

    for (int i = 0; i < 4; i++) {
        int din = DIMS[i], dout = DIMS[i + 1];
        int total = Nn * dout;
        bool isgat = (i == 0 || i == 2);
        float* h = hbuf[i];
        float* agg = aggbuf[i];

        run_gemm(xin, gcn_w[i], h, Nn, dout, din);
        cudaMemsetAsync(agg, 0, (size_t)total * sizeof(float));
        gcn_agg_kernel<<<warpGrid, 256>>>(h, row, col, dis, agg, Etot, E, dout);

        cudaMemsetAsync(bnsum, 0, dout * sizeof(float));
        cudaMemsetAsync(bnsq, 0, dout * sizeof(float));
        bn_stats_kernel<<<512, dout>>>(agg, bnsum, bnsq, Nn, dout);
        bn_finalize_kernel<<<1, dout>>>(bnsum, bnsq, bn_g[i], bn_b[i], scl, shf, dout,
                                        1.0f / (float)Nn);
        // y into h's buffer; relu only fused for non-GAT hidden layers
        int relu_here = (!isgat && i < 3) ? 1 : 0;
        bn_apply_kernel<<<cdiv(total, 256), 256>>>(agg, h, scl, shf, total, dout, relu_here);

        if (isgat) {
            int j = (i == 0) ? 0 : 1;
            float* hg = hgbuf[i];
            float* num = numbuf[i];
            run_gemm(h, gat_w[j], hg, Nn, dout, dout);
            gat_coef_kernel<<<cdiv(Nn * HEADS, 256), 256>>>(hg, gat_as[j], gat_ad[j],
                                                            asrc, adst, Nn, dout);
            gat_init_ms_kernel<<<cdiv(Nn * HEADS, 256), 256>>>(ms, ss, Nn * HEADS);
            gat_max_kernel<<<cdiv(Etot, 256), 256>>>(asrc, adst, row, col, ms, Etot, E);
            cudaMemsetAsync(num, 0, (size_t)total * sizeof(float));
            gat_accum_kernel<<<warpGrid, 256>>>(hg, asrc, adst, ms, ss, num, row, col,
                                                Etot, E, dout);
            gat_finalize_kernel<<<cdiv(total, 256), 256>>>(num, ss, gat_b[j], h, total, dout);
            xin = num;
        } else {
            xin = h;
        }
    }

    // global mean pool over batch -> [G, 64]
    const int dfin = DIMS[4];
    const int G = out_size / dfin;
    cudaMemsetAsync(pool, 0, (size_t)G * dfin * sizeof(float));
    cudaMemsetAsync(cnt, 0, (size_t)G * sizeof(float));
    pool_accum_kernel<<<cdiv(Nn * dfin, 256), 256>>>(xin, batch, pool, Nn, dfin);
    pool_cnt_kernel<<<cdiv(Nn, 256), 256>>>(batch, cnt, Nn);
    pool_final_kernel<<<cdiv(G * dfin, 256), 256>>>(pool, cnt, (float*)d_out, G, dfin);
}

// round 3
// speedup vs baseline: 2.5747x; 2.5747x over previous
#include <cuda_runtime.h>
#include <cuda_bf16.h>
#include <cstdint>

#define NMAX 100000
#define EMAX 1600000
#define ETOTMAX (NMAX + EMAX)
#define GMAX 256
#define HEADS 4
#define SCAN_BLK 512

// ---------------- scratch (device globals; no allocation allowed) -------------
__device__ float g_b0[NMAX * 128];
__device__ float g_b1[NMAX * 128];
__device__ float g_b2[NMAX * 128];
__device__ float g_dis[NMAX];
__device__ float g_asrc[NMAX * HEADS];
__device__ float g_adst[NMAX * HEADS];
__device__ float g_bnsum[128];
__device__ float g_bnsq[128];
__device__ float g_scale[128];
__device__ float g_shift[128];
__device__ float g_pool[GMAX * 64];
__device__ float g_cnt[GMAX];
// CSR structures
__device__ int   g_hist[NMAX];
__device__ int   g_off[NMAX + 1];
__device__ int   g_cur[NMAX];
__device__ int   g_csr_row[ETOTMAX];
__device__ float g_csr_nrm[ETOTMAX];
__device__ int   g_blksum[256];

// ---------------- helpers ----------------
__device__ __forceinline__ float lrelu(float v) { return v > 0.f ? v : 0.2f * v; }
static inline int cdiv(int a, int b) { return (a + b - 1) / b; }

// ---------------- CSR build ----------------
__global__ void fill_int_kernel(int* p, int v, int n) {
    int t = blockIdx.x * blockDim.x + threadIdx.x;
    if (t < n) p[t] = v;
}

__global__ void hist_kernel(const int* __restrict__ col, int* hist, int E) {
    int e = blockIdx.x * blockDim.x + threadIdx.x;
    if (e < E) atomicAdd(&hist[col[e]], 1);
}

__global__ void scan1_kernel(const int* __restrict__ hist, int* blksum, int Nn) {
    __shared__ int sm[SCAN_BLK];
    int i = blockIdx.x * SCAN_BLK + threadIdx.x;
    sm[threadIdx.x] = (i < Nn) ? hist[i] : 0;
    __syncthreads();
    for (int st = SCAN_BLK / 2; st > 0; st >>= 1) {
        if (threadIdx.x < st) sm[threadIdx.x] += sm[threadIdx.x + st];
        __syncthreads();
    }
    if (threadIdx.x == 0) blksum[blockIdx.x] = sm[0];
}

__global__ void scan2_kernel(int* blksum, int nb) {
    __shared__ int sm[256];
    int v = (threadIdx.x < nb) ? blksum[threadIdx.x] : 0;
    sm[threadIdx.x] = v;
    __syncthreads();
    for (int st = 1; st < 256; st <<= 1) {
        int t = (threadIdx.x >= st) ? sm[threadIdx.x - st] : 0;
        __syncthreads();
        sm[threadIdx.x] += t;
        __syncthreads();
    }
    if (threadIdx.x < nb) blksum[threadIdx.x] = sm[threadIdx.x] - v;  // exclusive
}

__global__ void scan3_kernel(const int* __restrict__ hist, const int* __restrict__ blksum,
                             int* off, int* cur, int* csr_row, float* csr_nrm,
                             float* dis, int Nn) {
    __shared__ int sm[SCAN_BLK];
    int i = blockIdx.x * SCAN_BLK + threadIdx.x;
    int v = (i < Nn) ? hist[i] : 0;
    sm[threadIdx.x] = v;
    __syncthreads();
    for (int st = 1; st < SCAN_BLK; st <<= 1) {
        int t = (threadIdx.x >= st) ? sm[threadIdx.x - st] : 0;
        __syncthreads();
        sm[threadIdx.x] += t;
        __syncthreads();
    }
    if (i < Nn) {
        int excl = sm[threadIdx.x] - v + blksum[blockIdx.x];
        off[i] = excl;
        cur[i] = excl + 1;              // slot excl reserved for self-loop
        dis[i] = rsqrtf((float)v);
        csr_row[excl] = i;
        csr_nrm[excl] = 1.0f / (float)v;  // dis[i]^2
        if (i == Nn - 1) off[Nn] = excl + v;
    }
}

__global__ void scatter_kernel(const int* __restrict__ row, const int* __restrict__ col,
                               const float* __restrict__ dis, int* cur,
                               int* csr_row, float* csr_nrm, int E) {
    int e = blockIdx.x * blockDim.x + threadIdx.x;
    if (e >= E) return;
    int r = row[e], c = col[e];
    int pos = atomicAdd(&cur[c], 1);
    csr_row[pos] = r;
    csr_nrm[pos] = dis[r] * dis[c];
}

// ---------------- GEMM: C[M,N] = A[M,K] @ B[K,N], 128x64 tile ----------------
__global__ void gemm_kernel(const float* __restrict__ A, const float* __restrict__ B,
                            float* __restrict__ C, int M, int N, int K) {
    __shared__ float As[16][129];
    __shared__ float Bs[16][64];
    int tid = threadIdx.x;
    int tx = tid & 15;   // N quad (16 * 4 = 64)
    int ty = tid >> 4;   // M group (16 * 8 = 128)
    int rowBase = blockIdx.y * 128;
    int colBase = blockIdx.x * 64;
    float acc[8][4] = {};
    for (int k0 = 0; k0 < K; k0 += 16) {
#pragma unroll
        for (int i = 0; i < 8; i++) {
            int idx = tid + i * 256;
            int r = idx >> 4, c = idx & 15;
            int gr = rowBase + r;
            As[c][r] = (gr < M) ? A[(size_t)gr * K + k0 + c] : 0.f;
        }
#pragma unroll
        for (int i = 0; i < 4; i++) {
            int idx = tid + i * 256;
            int r = idx >> 6, c = idx & 63;
            Bs[r][c] = B[(size_t)(k0 + r) * N + colBase + c];
        }
        __syncthreads();
#pragma unroll
        for (int kk = 0; kk < 16; kk++) {
            float4 b4 = *(const float4*)&Bs[kk][tx * 4];
            float a[8];
#pragma unroll
            for (int m = 0; m < 8; m++) a[m] = As[kk][ty * 8 + m];
#pragma unroll
            for (int m = 0; m < 8; m++) {
                acc[m][0] += a[m] * b4.x;
                acc[m][1] += a[m] * b4.y;
                acc[m][2] += a[m] * b4.z;
                acc[m][3] += a[m] * b4.w;
            }
        }
        __syncthreads();
    }
#pragma unroll
    for (int m = 0; m < 8; m++) {
        int gr = rowBase + ty * 8 + m;
        if (gr < M) {
            float4 v = make_float4(acc[m][0], acc[m][1], acc[m][2], acc[m][3]);
            *(float4*)&C[(size_t)gr * N + colBase + tx * 4] = v;
        }
    }
}

// ---------------- GCN aggregation: warp per node, CSR gather ----------------
template <int D>
__global__ void gcn_agg_csr_kernel(const float* __restrict__ h, const int* __restrict__ off,
                                   const int* __restrict__ csr_row,
                                   const float* __restrict__ csr_nrm,
                                   float* __restrict__ out, int Nn) {
    int node = (blockIdx.x * blockDim.x + threadIdx.x) >> 5;
    if (node >= Nn) return;
    int lane = threadIdx.x & 31;
    constexpr int V = D / 32;  // floats per lane: 2 or 4
    int s0 = off[node], s1 = off[node + 1];
    float acc[V] = {};
    for (int s = s0; s < s1; s++) {
        int r = csr_row[s];
        float nrm = csr_nrm[s];
        const float* hp = h + (size_t)r * D + lane * V;
        if (V == 4) {
            float4 v = *(const float4*)hp;
            acc[0] += v.x * nrm; acc[1] += v.y * nrm;
            acc[2] += v.z * nrm; acc[3] += v.w * nrm;
        } else {
            float2 v = *(const float2*)hp;
            acc[0] += v.x * nrm; acc[1] += v.y * nrm;
        }
    }
    float* op = out + (size_t)node * D + lane * V;
    if (V == 4) *(float4*)op = make_float4(acc[0], acc[1], acc[2], acc[3]);
    else        *(float2*)op = make_float2(acc[0], acc[1]);
}

// ---------------- BN ----------------
__global__ void bn_stats_kernel(const float* __restrict__ x, float* sum, float* sq,
                                int Nrows, int d) {
    int c = threadIdx.x;
    float s = 0.f, ss = 0.f;
    for (int r = blockIdx.x; r < Nrows; r += gridDim.x) {
        float v = x[(size_t)r * d + c];
        s += v; ss += v * v;
    }
    atomicAdd(&sum[c], s);
    atomicAdd(&sq[c], ss);
}

__global__ void bn_finalize_kernel(const float* sum, const float* sq,
                                   const float* __restrict__ g, const float* __restrict__ b,
                                   float* scale, float* shift, int d, float invN) {
    int c = threadIdx.x;
    if (c < d) {
        float mu = sum[c] * invN;
        float var = sq[c] * invN - mu * mu;
        float rs = rsqrtf(var + 1e-5f);
        float sc = g[c] * rs;
        scale[c] = sc;
        shift[c] = b[c] - mu * sc;
    }
}

__global__ void bn_apply_kernel(const float* __restrict__ xin, float* __restrict__ y,
                                const float* __restrict__ scale, const float* __restrict__ shift,
                                int total, int d, int relu) {
    int t = blockIdx.x * blockDim.x + threadIdx.x;
    if (t >= total) return;
    int c = t % d;
    float v = xin[t] * scale[c] + shift[c];
    if (relu) v = lrelu(v);
    y[t] = v;
}

// ---------------- GAT ----------------
__global__ void gat_coef_kernel(const float* __restrict__ hg, const float* __restrict__ a_src,
                                const float* __restrict__ a_dst, float* asrc, float* adst,
                                int Nn, int d) {
    int t = blockIdx.x * blockDim.x + threadIdx.x;
    if (t >= Nn * HEADS) return;
    int n = t >> 2, h = t & 3;
    int C = d >> 2;
    const float* hp = hg + (size_t)n * d + h * C;
    const float* as = a_src + h * C;
    const float* ad = a_dst + h * C;
    float s1 = 0.f, s2 = 0.f;
    for (int c = 0; c < C; c++) { float v = hp[c]; s1 += v * as[c]; s2 += v * ad[c]; }
    asrc[t] = s1;
    adst[t] = s2;
}

// Fully fused GAT: warp per node. 2 passes over incoming edges (max, then
// exp/accumulate), epilogue does alpha-normalize + bias + residual + lrelu.
template <int D>
__global__ void gat_csr_kernel(const float* __restrict__ hg, const float* __restrict__ asrc,
                               const float* __restrict__ adst, const int* __restrict__ off,
                               const int* __restrict__ csr_row, const float* __restrict__ gb,
                               const float* __restrict__ y, float* __restrict__ xout, int Nn) {
    int node = (blockIdx.x * blockDim.x + threadIdx.x) >> 5;
    if (node >= Nn) return;
    int lane = threadIdx.x & 31;
    constexpr int V = D / 32;
    int hh = lane >> 3;  // 8 lanes per head for both D=64 (C=16,V=2) and D=128 (C=32,V=4)
    int s0 = off[node], s1 = off[node + 1];
    float ad = adst[node * 4 + hh];
    // pass 1: per-head max
    float m = -1e30f;
    for (int s = s0; s < s1; s++) {
        int r = csr_row[s];
        float e = lrelu(asrc[r * 4 + hh] + ad);
        m = fmaxf(m, e);
    }
    // pass 2: weighted accumulation
    float acc[V] = {};
    float sw = 0.f;
    for (int s = s0; s < s1; s++) {
        int r = csr_row[s];
        float e = lrelu(asrc[r * 4 + hh] + ad);
        float w = __expf(e - m);
        sw += w;
        const float* hp = hg + (size_t)r * D + lane * V;
        if (V == 4) {
            float4 v = *(const float4*)hp;
            acc[0] += v.x * w; acc[1] += v.y * w;
            acc[2] += v.z * w; acc[3] += v.w * w;
        } else {
            float2 v = *(const float2*)hp;
            acc[0] += v.x * w; acc[1] += v.y * w;
        }
    }
    float inv = 1.f / sw;
    const float* yp = y + (size_t)node * D + lane * V;
    float* op = xout + (size_t)node * D + lane * V;
#pragma unroll
    for (int k = 0; k < V; k++) {
        float v = acc[k] * inv + gb[lane * V + k] + yp[k];
        op[k] = lrelu(v);
    }
}

// ---------------- pooling ----------------
__global__ void fill_kernel(float* p, float v, int n) {
    int t = blockIdx.x * blockDim.x + threadIdx.x;
    if (t < n) p[t] = v;
}

__global__ void pool_accum_kernel(const float* __restrict__ x, const int* __restrict__ batch,
                                  float* sums, int Nn, int d) {
    int t = blockIdx.x * blockDim.x + threadIdx.x;
    if (t >= Nn * d) return;
    int n = t / d, c = t % d;
    atomicAdd(&sums[batch[n] * d + c], x[t]);
}

__global__ void pool_cnt_kernel(const int* __restrict__ batch, float* cnt, int Nn) {
    int n = blockIdx.x * blockDim.x + threadIdx.x;
    if (n < Nn) atomicAdd(&cnt[batch[n]], 1.0f);
}

__global__ void pool_final_kernel(const float* __restrict__ sums, const float* __restrict__ cnt,
                                  float* __restrict__ out, int G, int d) {
    int t = blockIdx.x * blockDim.x + threadIdx.x;
    if (t >= G * d) return;
    int g = t / d;
    out[t] = sums[t] / fmaxf(cnt[g], 1.0f);
}

// ---------------- host orchestration ----------------
static void run_gemm(const float* A, const float* B, float* C, int M, int N, int K) {
    dim3 grid(cdiv(N, 64), cdiv(M, 128));
    gemm_kernel<<<grid, 256>>>(A, B, C, M, N, K);
}

extern "C" void kernel_launch(void* const* d_in, const int* in_sizes, int n_in,
                              void* d_out, int out_size) {
    const float* x_in  = (const float*)d_in[0];
    const int*   ei    = (const int*)d_in[1];
    const int*   batch = (const int*)d_in[2];
    const float* gcn_w[4], *bn_g[4], *bn_b[4];
    for (int i = 0; i < 4; i++) {
        gcn_w[i] = (const float*)d_in[3 + i * 4 + 0];
        bn_g[i]  = (const float*)d_in[3 + i * 4 + 2];
        bn_b[i]  = (const float*)d_in[3 + i * 4 + 3];
    }
    const float* gat_w[2], *gat_as[2], *gat_ad[2], *gat_b[2];
    for (int j = 0; j < 2; j++) {
        gat_w[j]  = (const float*)d_in[19 + j * 4 + 0];
        gat_as[j] = (const float*)d_in[19 + j * 4 + 1];
        gat_ad[j] = (const float*)d_in[19 + j * 4 + 2];
        gat_b[j]  = (const float*)d_in[19 + j * 4 + 3];
    }
    const int Nn = in_sizes[0] / 16;
    const int E  = in_sizes[1] / 2;
    const int* row = ei;
    const int* col = ei + E;
    const int DIMS[5] = {16, 64, 128, 128, 64};

    float *b0, *b1, *b2, *dis, *asrc, *adst;
    float *bnsum, *bnsq, *scl, *shf, *pool, *cnt;
    int *hist, *off, *cur, *csr_row, *blksum;
    float *csr_nrm;
    cudaGetSymbolAddress((void**)&b0, g_b0);
    cudaGetSymbolAddress((void**)&b1, g_b1);
    cudaGetSymbolAddress((void**)&b2, g_b2);
    cudaGetSymbolAddress((void**)&dis, g_dis);
    cudaGetSymbolAddress((void**)&asrc, g_asrc);
    cudaGetSymbolAddress((void**)&adst, g_adst);
    cudaGetSymbolAddress((void**)&bnsum, g_bnsum);
    cudaGetSymbolAddress((void**)&bnsq, g_bnsq);
    cudaGetSymbolAddress((void**)&scl, g_scale);
    cudaGetSymbolAddress((void**)&shf, g_shift);
    cudaGetSymbolAddress((void**)&pool, g_pool);
    cudaGetSymbolAddress((void**)&cnt, g_cnt);
    cudaGetSymbolAddress((void**)&hist, g_hist);
    cudaGetSymbolAddress((void**)&off, g_off);
    cudaGetSymbolAddress((void**)&cur, g_cur);
    cudaGetSymbolAddress((void**)&csr_row, g_csr_row);
    cudaGetSymbolAddress((void**)&csr_nrm, g_csr_nrm);
    cudaGetSymbolAddress((void**)&blksum, g_blksum);

    // ---- CSR build (by target node `col`), self-loops at segment head ----
    const int nb = cdiv(Nn, SCAN_BLK);
    fill_int_kernel<<<cdiv(Nn, 256), 256>>>(hist, 1, Nn);         // self-loop
    hist_kernel<<<cdiv(E, 256), 256>>>(col, hist, E);
    scan1_kernel<<<nb, SCAN_BLK>>>(hist, blksum, Nn);
    scan2_kernel<<<1, 256>>>(blksum, nb);
    scan3_kernel<<<nb, SCAN_BLK>>>(hist, blksum, off, cur, csr_row, csr_nrm, dis, Nn);
    scatter_kernel<<<cdiv(E, 256), 256>>>(row, col, dis, cur, csr_row, csr_nrm, E);

    const int nodeWarpGrid = cdiv(Nn * 32, 256);

    // layer buffer plan (same as R1):
    //  i=0: xin=x(ext) h=b0 agg=b1 y=b0 hg=b1 xnext=b2
    //  i=1: xin=b2     h=b0 agg=b1 y=b0 xnext=b0
    //  i=2: xin=b0     h=b1 agg=b2 y=b1 hg=b2 xnext=b0
    //  i=3: xin=b0     h=b1 agg=b2 y=b1 final=b1
    const float* xin = x_in;
    float* hbuf[4]   = {b0, b0, b1, b1};
    float* aggbuf[4] = {b1, b1, b2, b2};
    float* hgbuf[4]  = {b1, 0, b2, 0};
    float* numbuf[4] = {b2, 0, b0, 0};

    for (int i = 0; i < 4; i++) {
        int din = DIMS[i], dout = DIMS[i + 1];
        int total = Nn * dout;
        bool isgat = (i == 0 || i == 2);
        float* h = hbuf[i];
        float* agg = aggbuf[i];

        run_gemm(xin, gcn_w[i], h, Nn, dout, din);
        if (dout == 64)
            gcn_agg_csr_kernel<64><<<nodeWarpGrid, 256>>>(h, off, csr_row, csr_nrm, agg, Nn);
        else
            gcn_agg_csr_kernel<128><<<nodeWarpGrid, 256>>>(h, off, csr_row, csr_nrm, agg, Nn);

        cudaMemsetAsync(bnsum, 0, dout * sizeof(float));
        cudaMemsetAsync(bnsq, 0, dout * sizeof(float));
        bn_stats_kernel<<<512, dout>>>(agg, bnsum, bnsq, Nn, dout);
        bn_finalize_kernel<<<1, dout>>>(bnsum, bnsq, bn_g[i], bn_b[i], scl, shf, dout,
                                        1.0f / (float)Nn);
        int relu_here = (!isgat && i < 3) ? 1 : 0;
        bn_apply_kernel<<<cdiv(total, 256), 256>>>(agg, h, scl, shf, total, dout, relu_here);

        if (isgat) {
            int j = (i == 0) ? 0 : 1;
            float* hg = hgbuf[i];
            float* xnext = numbuf[i];
            run_gemm(h, gat_w[j], hg, Nn, dout, dout);
            gat_coef_kernel<<<cdiv(Nn * HEADS, 256), 256>>>(hg, gat_as[j], gat_ad[j],
                                                            asrc, adst, Nn, dout);
            if (dout == 64)
                gat_csr_kernel<64><<<nodeWarpGrid, 256>>>(hg, asrc, adst, off, csr_row,
                                                          gat_b[j], h, xnext, Nn);
            else
                gat_csr_kernel<128><<<nodeWarpGrid, 256>>>(hg, asrc, adst, off, csr_row,
                                                           gat_b[j], h, xnext, Nn);
            xin = xnext;
        } else {
            xin = h;
        }
    }

    // global mean pool over batch -> [G, 64]
    const int dfin = DIMS[4];
    const int G = out_size / dfin;
    cudaMemsetAsync(pool, 0, (size_t)G * dfin * sizeof(float));
    cudaMemsetAsync(cnt, 0, (size_t)G * sizeof(float));
    pool_accum_kernel<<<cdiv(Nn * dfin, 256), 256>>>(xin, batch, pool, Nn, dfin);
    pool_cnt_kernel<<<cdiv(Nn, 256), 256>>>(batch, cnt, Nn);
    pool_final_kernel<<<cdiv(G * dfin, 256), 256>>>(pool, cnt, (float*)d_out, G, dfin);
}

// round 4
// speedup vs baseline: 2.9102x; 1.1303x over previous
#include <cuda_runtime.h>
#include <cuda_bf16.h>
#include <cstdint>

#define NMAX 100000
#define EMAX 1600000
#define ETOTMAX (NMAX + EMAX)
#define GMAX 256
#define HEADS 4
#define SCAN_BLK 512

// ---------------- scratch (device globals; no allocation allowed) -------------
__device__ float g_b0[NMAX * 128];
__device__ float g_b1[NMAX * 128];
__device__ float g_b2[NMAX * 128];
__device__ float g_dis[NMAX];
__device__ float g_asrc[NMAX * HEADS];
__device__ float g_adst[NMAX * HEADS];
__device__ float g_bnsum[128];
__device__ float g_bnsq[128];
__device__ float g_scale[128];
__device__ float g_shift[128];
__device__ float g_pool[GMAX * 64];
__device__ float g_cnt[GMAX];
__device__ int   g_hist[NMAX];
__device__ int   g_off[NMAX + 1];
__device__ int   g_cur[NMAX];
__device__ int   g_csr_row[ETOTMAX];
__device__ float g_csr_nrm[ETOTMAX];
__device__ int   g_blksum[256];

// ---------------- helpers ----------------
__device__ __forceinline__ float lrelu(float v) { return v > 0.f ? v : 0.2f * v; }
static inline int cdiv(int a, int b) { return (a + b - 1) / b; }

// ---------------- CSR build ----------------
__global__ void fill_int_kernel(int* p, int v, int n) {
    int t = blockIdx.x * blockDim.x + threadIdx.x;
    if (t < n) p[t] = v;
}

__global__ void hist_kernel(const int* __restrict__ col, int* hist, int E) {
    int e = blockIdx.x * blockDim.x + threadIdx.x;
    if (e < E) atomicAdd(&hist[col[e]], 1);
}

__global__ void scan1_kernel(const int* __restrict__ hist, int* blksum, int Nn) {
    __shared__ int sm[SCAN_BLK];
    int i = blockIdx.x * SCAN_BLK + threadIdx.x;
    sm[threadIdx.x] = (i < Nn) ? hist[i] : 0;
    __syncthreads();
    for (int st = SCAN_BLK / 2; st > 0; st >>= 1) {
        if (threadIdx.x < st) sm[threadIdx.x] += sm[threadIdx.x + st];
        __syncthreads();
    }
    if (threadIdx.x == 0) blksum[blockIdx.x] = sm[0];
}

__global__ void scan2_kernel(int* blksum, int nb) {
    __shared__ int sm[256];
    int v = (threadIdx.x < nb) ? blksum[threadIdx.x] : 0;
    sm[threadIdx.x] = v;
    __syncthreads();
    for (int st = 1; st < 256; st <<= 1) {
        int t = (threadIdx.x >= st) ? sm[threadIdx.x - st] : 0;
        __syncthreads();
        sm[threadIdx.x] += t;
        __syncthreads();
    }
    if (threadIdx.x < nb) blksum[threadIdx.x] = sm[threadIdx.x] - v;  // exclusive
}

__global__ void scan3_kernel(const int* __restrict__ hist, const int* __restrict__ blksum,
                             int* off, int* cur, int* csr_row, float* csr_nrm,
                             float* dis, int Nn) {
    __shared__ int sm[SCAN_BLK];
    int i = blockIdx.x * SCAN_BLK + threadIdx.x;
    int v = (i < Nn) ? hist[i] : 0;
    sm[threadIdx.x] = v;
    __syncthreads();
    for (int st = 1; st < SCAN_BLK; st <<= 1) {
        int t = (threadIdx.x >= st) ? sm[threadIdx.x - st] : 0;
        __syncthreads();
        sm[threadIdx.x] += t;
        __syncthreads();
    }
    if (i < Nn) {
        int excl = sm[threadIdx.x] - v + blksum[blockIdx.x];
        off[i] = excl;
        cur[i] = excl + 1;              // slot excl reserved for self-loop
        dis[i] = rsqrtf((float)v);
        csr_row[excl] = i;
        csr_nrm[excl] = 1.0f / (float)v;
        if (i == Nn - 1) off[Nn] = excl + v;
    }
}

__global__ void scatter_kernel(const int* __restrict__ row, const int* __restrict__ col,
                               const float* __restrict__ dis, int* cur,
                               int* csr_row, float* csr_nrm, int E) {
    int e = blockIdx.x * blockDim.x + threadIdx.x;
    if (e >= E) return;
    int r = row[e], c = col[e];
    int pos = atomicAdd(&cur[c], 1);
    csr_row[pos] = r;
    csr_nrm[pos] = dis[r] * dis[c];
}

// ---------------- GEMM ----------------
// C[M,N] = op(A)[M,K] @ B[K,N].  MODE: 0 = raw A, 1 = A*scl+shf, 2 = lrelu(A*scl+shf)
// 256 threads, 16x16 thread grid, micro-tile TM x TN.
template <int BM, int BN, int MODE>
__global__ void __launch_bounds__(256) gemm_kernel(
    const float* __restrict__ A, const float* __restrict__ B, float* __restrict__ C,
    const float* __restrict__ scl, const float* __restrict__ shf, int M, int N, int K) {
    constexpr int TM = BM / 16, TN = BN / 16;
    __shared__ float As[16][BM + 4];
    __shared__ float Bs[16][BN];
    int tid = threadIdx.x;
    int tx = tid & 15, ty = tid >> 4;
    int rowBase = blockIdx.y * BM;
    int colBase = blockIdx.x * BN;
    float acc[TM][TN] = {};
    for (int k0 = 0; k0 < K; k0 += 16) {
        constexpr int ALOADS = BM * 4 / 256;  // float4 loads per thread
#pragma unroll
        for (int i = 0; i < ALOADS; i++) {
            int idx = tid + i * 256;
            int r = idx >> 2, q = idx & 3;
            int gr = rowBase + r;
            float4 v = make_float4(0.f, 0.f, 0.f, 0.f);
            if (gr < M) v = *(const float4*)&A[(size_t)gr * K + k0 + q * 4];
            if (MODE >= 1) {
                float4 s4 = *(const float4*)&scl[k0 + q * 4];
                float4 h4 = *(const float4*)&shf[k0 + q * 4];
                v.x = v.x * s4.x + h4.x; v.y = v.y * s4.y + h4.y;
                v.z = v.z * s4.z + h4.z; v.w = v.w * s4.w + h4.w;
                if (MODE == 2) { v.x = lrelu(v.x); v.y = lrelu(v.y); v.z = lrelu(v.z); v.w = lrelu(v.w); }
            }
            As[q * 4 + 0][r] = v.x; As[q * 4 + 1][r] = v.y;
            As[q * 4 + 2][r] = v.z; As[q * 4 + 3][r] = v.w;
        }
        constexpr int BLOADS = BN * 16 / 4 / 256;
#pragma unroll
        for (int i = 0; i < BLOADS; i++) {
            int idx = tid + i * 256;
            int r = idx / (BN / 4), c = idx % (BN / 4);
            *(float4*)&Bs[r][c * 4] = *(const float4*)&B[(size_t)(k0 + r) * N + colBase + c * 4];
        }
        __syncthreads();
#pragma unroll
        for (int kk = 0; kk < 16; kk++) {
            float a[TM], b[TN];
#pragma unroll
            for (int m = 0; m < TM; m += 4)
                *(float4*)&a[m] = *(const float4*)&As[kk][ty * TM + m];
#pragma unroll
            for (int n = 0; n < TN; n += 4)
                *(float4*)&b[n] = *(const float4*)&Bs[kk][tx * TN + n];
#pragma unroll
            for (int m = 0; m < TM; m++)
#pragma unroll
                for (int n = 0; n < TN; n++) acc[m][n] += a[m] * b[n];
        }
        __syncthreads();
    }
#pragma unroll
    for (int m = 0; m < TM; m++) {
        int gr = rowBase + ty * TM + m;
        if (gr < M) {
#pragma unroll
            for (int n = 0; n < TN; n += 4) {
                float4 v = make_float4(acc[m][n], acc[m][n + 1], acc[m][n + 2], acc[m][n + 3]);
                *(float4*)&C[(size_t)gr * N + colBase + tx * TN + n] = v;
            }
        }
    }
}

// ---------------- GCN aggregation: warp per node, CSR gather ----------------
template <int D>
__global__ void gcn_agg_csr_kernel(const float* __restrict__ h, const int* __restrict__ off,
                                   const int* __restrict__ csr_row,
                                   const float* __restrict__ csr_nrm,
                                   float* __restrict__ out, int Nn) {
    int node = (blockIdx.x * blockDim.x + threadIdx.x) >> 5;
    if (node >= Nn) return;
    int lane = threadIdx.x & 31;
    constexpr int V = D / 32;
    int s0 = off[node], s1 = off[node + 1];
    float acc[V] = {};
    for (int s = s0; s < s1; s++) {
        int r = csr_row[s];
        float nrm = csr_nrm[s];
        const float* hp = h + (size_t)r * D + lane * V;
        if (V == 4) {
            float4 v = *(const float4*)hp;
            acc[0] += v.x * nrm; acc[1] += v.y * nrm;
            acc[2] += v.z * nrm; acc[3] += v.w * nrm;
        } else {
            float2 v = *(const float2*)hp;
            acc[0] += v.x * nrm; acc[1] += v.y * nrm;
        }
    }
    float* op = out + (size_t)node * D + lane * V;
    if (V == 4) *(float4*)op = make_float4(acc[0], acc[1], acc[2], acc[3]);
    else        *(float2*)op = make_float2(acc[0], acc[1]);
}

// ---------------- BN stats ----------------
__global__ void bn_stats_kernel(const float* __restrict__ x, float* sum, float* sq,
                                int Nrows, int d) {
    int c = threadIdx.x;
    float s = 0.f, ss = 0.f;
    for (int r = blockIdx.x; r < Nrows; r += gridDim.x) {
        float v = x[(size_t)r * d + c];
        s += v; ss += v * v;
    }
    atomicAdd(&sum[c], s);
    atomicAdd(&sq[c], ss);
}

__global__ void bn_finalize_kernel(const float* sum, const float* sq,
                                   const float* __restrict__ g, const float* __restrict__ b,
                                   float* scale, float* shift, int d, float invN) {
    int c = threadIdx.x;
    if (c < d) {
        float mu = sum[c] * invN;
        float var = sq[c] * invN - mu * mu;
        float rs = rsqrtf(var + 1e-5f);
        float sc = g[c] * rs;
        scale[c] = sc;
        shift[c] = b[c] - mu * sc;
    }
}

// ---------------- GAT ----------------
__global__ void gat_coef_kernel(const float* __restrict__ hg, const float* __restrict__ a_src,
                                const float* __restrict__ a_dst, float* asrc, float* adst,
                                int Nn, int d) {
    int t = blockIdx.x * blockDim.x + threadIdx.x;
    if (t >= Nn * HEADS) return;
    int n = t >> 2, h = t & 3;
    int C = d >> 2;
    const float* hp = hg + (size_t)n * d + h * C;
    const float* as = a_src + h * C;
    const float* ad = a_dst + h * C;
    float s1 = 0.f, s2 = 0.f;
    for (int c = 0; c < C; c++) { float v = hp[c]; s1 += v * as[c]; s2 += v * ad[c]; }
    asrc[t] = s1;
    adst[t] = s2;
}

// One-pass fused GAT: warp per node. w = exp(e) directly (softmax shift-invariant;
// |e| is small here so no overflow). Epilogue: normalize + bias + BN'd residual + lrelu.
template <int D>
__global__ void gat_csr_kernel(const float* __restrict__ hg, const float* __restrict__ asrc,
                               const float* __restrict__ adst, const int* __restrict__ off,
                               const int* __restrict__ csr_row, const float* __restrict__ gb,
                               const float* __restrict__ agg, const float* __restrict__ scl,
                               const float* __restrict__ shf, float* __restrict__ xout, int Nn) {
    int node = (blockIdx.x * blockDim.x + threadIdx.x) >> 5;
    if (node >= Nn) return;
    int lane = threadIdx.x & 31;
    constexpr int V = D / 32;
    int hh = lane >> 3;  // 8 lanes per head
    int s0 = off[node], s1 = off[node + 1];
    float ad = adst[node * 4 + hh];
    float acc[V] = {};
    float sw = 0.f;
    for (int s = s0; s < s1; s++) {
        int r = csr_row[s];
        float e = lrelu(asrc[r * 4 + hh] + ad);
        float w = __expf(e);
        sw += w;
        const float* hp = hg + (size_t)r * D + lane * V;
        if (V == 4) {
            float4 v = *(const float4*)hp;
            acc[0] += v.x * w; acc[1] += v.y * w;
            acc[2] += v.z * w; acc[3] += v.w * w;
        } else {
            float2 v = *(const float2*)hp;
            acc[0] += v.x * w; acc[1] += v.y * w;
        }
    }
    float inv = 1.f / sw;
    const float* ap = agg + (size_t)node * D + lane * V;
    float* op = xout + (size_t)node * D + lane * V;
#pragma unroll
    for (int k = 0; k < V; k++) {
        int c = lane * V + k;
        float y = ap[k] * scl[c] + shf[c];   // BN'd residual recomputed inline
        float v = acc[k] * inv + gb[c] + y;
        op[k] = lrelu(v);
    }
}

// ---------------- pooling (BN of last layer fused) ----------------
__global__ void pool_accum_bn_kernel(const float* __restrict__ x, const int* __restrict__ batch,
                                     const float* __restrict__ scl, const float* __restrict__ shf,
                                     float* sums, int Nn, int d) {
    int t = blockIdx.x * blockDim.x + threadIdx.x;
    if (t >= Nn * d) return;
    int n = t / d, c = t % d;
    atomicAdd(&sums[batch[n] * d + c], x[t] * scl[c] + shf[c]);
}

__global__ void pool_cnt_kernel(const int* __restrict__ batch, float* cnt, int Nn) {
    int n = blockIdx.x * blockDim.x + threadIdx.x;
    if (n < Nn) atomicAdd(&cnt[batch[n]], 1.0f);
}

__global__ void pool_final_kernel(const float* __restrict__ sums, const float* __restrict__ cnt,
                                  float* __restrict__ out, int G, int d) {
    int t = blockIdx.x * blockDim.x + threadIdx.x;
    if (t >= G * d) return;
    int g = t / d;
    out[t] = sums[t] / fmaxf(cnt[g], 1.0f);
}

// ---------------- host orchestration ----------------
extern "C" void kernel_launch(void* const* d_in, const int* in_sizes, int n_in,
                              void* d_out, int out_size) {
    const float* x_in  = (const float*)d_in[0];
    const int*   ei    = (const int*)d_in[1];
    const int*   batch = (const int*)d_in[2];
    const float* gcn_w[4], *bn_g[4], *bn_b[4];
    for (int i = 0; i < 4; i++) {
        gcn_w[i] = (const float*)d_in[3 + i * 4 + 0];
        bn_g[i]  = (const float*)d_in[3 + i * 4 + 2];
        bn_b[i]  = (const float*)d_in[3 + i * 4 + 3];
    }
    const float* gat_w[2], *gat_as[2], *gat_ad[2], *gat_b[2];
    for (int j = 0; j < 2; j++) {
        gat_w[j]  = (const float*)d_in[19 + j * 4 + 0];
        gat_as[j] = (const float*)d_in[19 + j * 4 + 1];
        gat_ad[j] = (const float*)d_in[19 + j * 4 + 2];
        gat_b[j]  = (const float*)d_in[19 + j * 4 + 3];
    }
    const int Nn = in_sizes[0] / 16;
    const int E  = in_sizes[1] / 2;
    const int* row = ei;
    const int* col = ei + E;

    float *b0, *b1, *b2, *dis, *asrc, *adst;
    float *bnsum, *bnsq, *scl, *shf, *pool, *cnt;
    int *hist, *off, *cur, *csr_row, *blksum;
    float *csr_nrm;
    cudaGetSymbolAddress((void**)&b0, g_b0);
    cudaGetSymbolAddress((void**)&b1, g_b1);
    cudaGetSymbolAddress((void**)&b2, g_b2);
    cudaGetSymbolAddress((void**)&dis, g_dis);
    cudaGetSymbolAddress((void**)&asrc, g_asrc);
    cudaGetSymbolAddress((void**)&adst, g_adst);
    cudaGetSymbolAddress((void**)&bnsum, g_bnsum);
    cudaGetSymbolAddress((void**)&bnsq, g_bnsq);
    cudaGetSymbolAddress((void**)&scl, g_scale);
    cudaGetSymbolAddress((void**)&shf, g_shift);
    cudaGetSymbolAddress((void**)&pool, g_pool);
    cudaGetSymbolAddress((void**)&cnt, g_cnt);
    cudaGetSymbolAddress((void**)&hist, g_hist);
    cudaGetSymbolAddress((void**)&off, g_off);
    cudaGetSymbolAddress((void**)&cur, g_cur);
    cudaGetSymbolAddress((void**)&csr_row, g_csr_row);
    cudaGetSymbolAddress((void**)&csr_nrm, g_csr_nrm);
    cudaGetSymbolAddress((void**)&blksum, g_blksum);

    // ---- CSR build (by target node), self-loop at segment head ----
    const int nb = cdiv(Nn, SCAN_BLK);
    fill_int_kernel<<<cdiv(Nn, 256), 256>>>(hist, 1, Nn);
    hist_kernel<<<cdiv(E, 256), 256>>>(col, hist, E);
    scan1_kernel<<<nb, SCAN_BLK>>>(hist, blksum, Nn);
    scan2_kernel<<<1, 256>>>(blksum, nb);
    scan3_kernel<<<nb, SCAN_BLK>>>(hist, blksum, off, cur, csr_row, csr_nrm, dis, Nn);
    scatter_kernel<<<cdiv(E, 256), 256>>>(row, col, dis, cur, csr_row, csr_nrm, E);

    const int nodeWarpGrid = cdiv(Nn * 32, 256);

    auto stats = [&](const float* agg, int i, int dout) {
        cudaMemsetAsync(bnsum, 0, dout * sizeof(float));
        cudaMemsetAsync(bnsq, 0, dout * sizeof(float));
        bn_stats_kernel<<<512, dout>>>(agg, bnsum, bnsq, Nn, dout);
        bn_finalize_kernel<<<1, dout>>>(bnsum, bnsq, bn_g[i], bn_b[i], scl, shf, dout,
                                        1.0f / (float)Nn);
    };

    // ---- layer 0: GCN(16->64) + BN + GAT + lrelu ----
    gemm_kernel<256, 64, 0><<<dim3(1, cdiv(Nn, 256)), 256>>>(x_in, gcn_w[0], b0, scl, shf, Nn, 64, 16);
    gcn_agg_csr_kernel<64><<<nodeWarpGrid, 256>>>(b0, off, csr_row, csr_nrm, b1, Nn);
    stats(b1, 0, 64);
    gemm_kernel<256, 64, 1><<<dim3(1, cdiv(Nn, 256)), 256>>>(b1, gat_w[0], b0, scl, shf, Nn, 64, 64);
    gat_coef_kernel<<<cdiv(Nn * HEADS, 256), 256>>>(b0, gat_as[0], gat_ad[0], asrc, adst, Nn, 64);
    gat_csr_kernel<64><<<nodeWarpGrid, 256>>>(b0, asrc, adst, off, csr_row, gat_b[0],
                                              b1, scl, shf, b2, Nn);

    // ---- layer 1: GCN(64->128) + BN + lrelu (relu fused into next gemm) ----
    gemm_kernel<128, 128, 0><<<dim3(1, cdiv(Nn, 128)), 256>>>(b2, gcn_w[1], b0, scl, shf, Nn, 128, 64);
    gcn_agg_csr_kernel<128><<<nodeWarpGrid, 256>>>(b0, off, csr_row, csr_nrm, b1, Nn);
    stats(b1, 1, 128);

    // ---- layer 2: GCN(128->128) [A = lrelu(BN(agg1))] + BN + GAT + lrelu ----
    gemm_kernel<128, 128, 2><<<dim3(1, cdiv(Nn, 128)), 256>>>(b1, gcn_w[2], b0, scl, shf, Nn, 128, 128);
    gcn_agg_csr_kernel<128><<<nodeWarpGrid, 256>>>(b0, off, csr_row, csr_nrm, b2, Nn);
    stats(b2, 2, 128);
    gemm_kernel<128, 128, 1><<<dim3(1, cdiv(Nn, 128)), 256>>>(b2, gat_w[1], b0, scl, shf, Nn, 128, 128);
    gat_coef_kernel<<<cdiv(Nn * HEADS, 256), 256>>>(b0, gat_as[1], gat_ad[1], asrc, adst, Nn, 128);
    gat_csr_kernel<128><<<nodeWarpGrid, 256>>>(b0, asrc, adst, off, csr_row, gat_b[1],
                                               b2, scl, shf, b1, Nn);

    // ---- layer 3: GCN(128->64) + BN (no relu, fused into pooling) ----
    gemm_kernel<256, 64, 0><<<dim3(1, cdiv(Nn, 256)), 256>>>(b1, gcn_w[3], b2, scl, shf, Nn, 64, 128);
    gcn_agg_csr_kernel<64><<<nodeWarpGrid, 256>>>(b2, off, csr_row, csr_nrm, b0, Nn);
    stats(b0, 3, 64);

    // ---- global mean pool (BN fused) ----
    const int dfin = 64;
    const int G = out_size / dfin;
    cudaMemsetAsync(pool, 0, (size_t)G * dfin * sizeof(float));
    cudaMemsetAsync(cnt, 0, (size_t)G * sizeof(float));
    pool_accum_bn_kernel<<<cdiv(Nn * dfin, 256), 256>>>(b0, batch, scl, shf, pool, Nn, dfin);
    pool_cnt_kernel<<<cdiv(Nn, 256), 256>>>(batch, cnt, Nn);
    pool_final_kernel<<<cdiv(G * dfin, 256), 256>>>(pool, cnt, (float*)d_out, G, dfin);
}